// round 4
// baseline (speedup 1.0000x reference)
#include <cuda_runtime.h>
#include <math.h>
#include <stdint.h>

#define Nn 8192
#define IN_FEAT 128
#define OUTF 64
#define LALPHA 0.2f
#define NEG_BIG (-9e15f)

#define BI 32          // rows per tile
#define BJ 128         // j-chunk
#define JS 2           // j-split: CTAs per tile
#define NCH ((Nn/JS)/BJ)   // 32 chunks per CTA
#define TPB 256
#define HST 72         // hs stride; 72 % 32 == 8 -> B-frag LDS conflict-free
#define PST 132        // ps stride; 132 % 32 == 4 -> A-frag LDS conflict-free
#define SMEM_BYTES ((BJ*HST + 2*BI*PST)*4)

// Scratch (device globals — no allocation allowed)
__device__ float g_htf[Nn*OUTF];            // h pre-rounded to tf32
__device__ float g_si[Nn];
__device__ float g_sj[Nn];
__device__ unsigned g_sjmax_enc;            // order-preserving unsigned encoding
__device__ float g_pacc[(Nn/BI)*JS*BI*OUTF]; // partial P@H per split CTA
__device__ float g_pl[(Nn/BI)*JS*BI];        // partial row sums

__device__ __forceinline__ uint32_t f2tf(float x) {
    uint32_t r;
    asm("cvt.rna.tf32.f32 %0, %1;" : "=r"(r) : "f"(x));
    return r;
}
__device__ __forceinline__ unsigned enc_f(float x) {
    unsigned u = __float_as_uint(x);
    return (u & 0x80000000u) ? ~u : (u | 0x80000000u);
}
__device__ __forceinline__ float dec_f(unsigned u) {
    return __uint_as_float((u & 0x80000000u) ? (u & 0x7FFFFFFFu) : ~u);
}
__device__ __forceinline__ void mma_tf32(float* c,
                                         uint32_t a0, uint32_t a1, uint32_t a2, uint32_t a3,
                                         uint32_t b0, uint32_t b1) {
    asm volatile(
        "mma.sync.aligned.m16n8k8.row.col.f32.tf32.tf32.f32 "
        "{%0,%1,%2,%3}, {%4,%5,%6,%7}, {%8,%9}, {%0,%1,%2,%3};"
        : "+f"(c[0]), "+f"(c[1]), "+f"(c[2]), "+f"(c[3])
        : "r"(a0), "r"(a1), "r"(a2), "r"(a3), "r"(b0), "r"(b1));
}

// ---------------------------------------------------------------------------
// K1: h = features @ W.T (stored as tf32), fused s_i/s_j + global max(s_j)
// ---------------------------------------------------------------------------
__global__ void __launch_bounds__(256) k_h(const float* __restrict__ feat,
                                           const float* __restrict__ W,
                                           const float* __restrict__ avec) {
    __shared__ float Wt[IN_FEAT][OUTF];
    __shared__ float sjred[32];
    int t = threadIdx.x;
#pragma unroll
    for (int w = 0; w < 8; w++) {
        int idx = t + 256 * w;
        int f   = idx >> 5;
        int c4  = idx & 31;
        float4 wv = ((const float4*)W)[idx];
        int k = c4 * 4;
        Wt[k + 0][f] = wv.x;
        Wt[k + 1][f] = wv.y;
        Wt[k + 2][f] = wv.z;
        Wt[k + 3][f] = wv.w;
    }
    __syncthreads();

    int il = t >> 3;
    int fo = t & 7;
    int i  = blockIdx.x * 32 + il;
    const float4* fr = (const float4*)(feat + (size_t)i * IN_FEAT);

    float acc[8];
#pragma unroll
    for (int c = 0; c < 8; c++) acc[c] = 0.f;

#pragma unroll
    for (int kk = 0; kk < 32; kk++) {
        float4 fv = fr[kk];
#pragma unroll
        for (int c = 0; c < 4; c++) {
            float fc = (c == 0) ? fv.x : (c == 1) ? fv.y : (c == 2) ? fv.z : fv.w;
            int k = kk * 4 + c;
            float4 w0 = *(const float4*)&Wt[k][fo * 8];
            float4 w1 = *(const float4*)&Wt[k][fo * 8 + 4];
            acc[0] += fc * w0.x; acc[1] += fc * w0.y;
            acc[2] += fc * w0.z; acc[3] += fc * w0.w;
            acc[4] += fc * w1.x; acc[5] += fc * w1.y;
            acc[6] += fc * w1.z; acc[7] += fc * w1.w;
        }
    }
    // store tf32-rounded h
    uint4 o0, o1;
    o0.x = f2tf(acc[0]); o0.y = f2tf(acc[1]); o0.z = f2tf(acc[2]); o0.w = f2tf(acc[3]);
    o1.x = f2tf(acc[4]); o1.y = f2tf(acc[5]); o1.z = f2tf(acc[6]); o1.w = f2tf(acc[7]);
    *(uint4*)(g_htf + (size_t)i * OUTF + fo * 8)     = o0;
    *(uint4*)(g_htf + (size_t)i * OUTF + fo * 8 + 4) = o1;

    // fused: s_i = h.a[:64], s_j = h.a[64:]  (full fp32 h)
    float sx = 0.f, sy = 0.f;
#pragma unroll
    for (int c = 0; c < 8; c++) {
        sx += acc[c] * avec[fo * 8 + c];
        sy += acc[c] * avec[OUTF + fo * 8 + c];
    }
#pragma unroll
    for (int o = 4; o > 0; o >>= 1) {
        sx += __shfl_down_sync(0xffffffffu, sx, o, 8);
        sy += __shfl_down_sync(0xffffffffu, sy, o, 8);
    }
    if (fo == 0) {
        g_si[i] = sx;
        g_sj[i] = sy;
        sjred[il] = sy;
    }
    __syncthreads();
    if (t == 0) {
        float m = sjred[0];
#pragma unroll
        for (int c = 1; c < 32; c++) m = fmaxf(m, sjred[c]);
        atomicMax(&g_sjmax_enc, enc_f(m));   // idempotent across replays
    }
}

// ---------------------------------------------------------------------------
// K2: scores + fixed-shift softmax numerator + tf32 MMA P@H -> partials
// Grid: 512 CTAs (tile = bid>>1, j-half = bid&1), 3 CTAs/SM.
// ---------------------------------------------------------------------------
__global__ void __launch_bounds__(TPB, 3) k_main(const float* __restrict__ geo,
                                                 const float* __restrict__ sem) {
    extern __shared__ float smem[];
    float* hs  = smem;                      // [BJ][HST] tf32 h chunk (single buffer)
    float* ps0 = smem + BJ * HST;           // [BI][PST] tf32 p tile, buffer 0
    float* ps1 = ps0 + BI * PST;            // buffer 1

    __shared__ float sjs[BJ];

    int t     = threadIdx.x;
    int bid   = blockIdx.x;
    int tile  = bid >> 1;
    int half  = bid & 1;
    int i0    = tile * BI;
    int jbase = half * (Nn / JS);
    int lane  = t & 31;
    int warp  = t >> 5;

    // ---- score mapping: 8 threads/row ----
    int r = t >> 3;
    int q = t & 7;
    float si_r  = g_si[i0 + r];
    float m_r   = fmaxf(0.f, 2.f * (si_r + dec_f(g_sjmax_enc)));
    float l_acc = 0.f;
    const float4* gbase = (const float4*)(geo + (size_t)(i0 + r) * Nn) + (jbase >> 2);
    const float4* sbase = (const float4*)(sem + (size_t)(i0 + r) * Nn) + (jbase >> 2);

    // ---- staging mapping ----
    int jr = t >> 4, f4 = t & 15;

    // ---- gemm mapping: 8 warps = 2(m) x 4(n), warp tile m16 x n16 ----
    int wm = warp & 1, wn = warp >> 1;
    int m0 = wm * 16, n0 = wn * 16;
    int ar = lane >> 2, ac = lane & 3;
    int bk = lane & 3,  bn = lane >> 2;

    float acc[2][4];
#pragma unroll
    for (int a = 0; a < 2; a++)
#pragma unroll
        for (int b = 0; b < 4; b++) acc[a][b] = 0.f;

    // prefetch adjacency chunk 0
    float4 gv[4], sv[4];
#pragma unroll
    for (int kk = 0; kk < 4; kk++) {
        gv[kk] = __ldcs(&gbase[q + 8 * kk]);
        sv[kk] = __ldcs(&sbase[q + 8 * kk]);
    }

    int buf = 0;
    for (int ci = 0; ci < NCH; ci++, buf ^= 1) {
        int jc = jbase + ci * BJ;
        float* psb = buf ? ps1 : ps0;

        __syncthreads();   // GEMM(ci-1) done reading hs & ps[buf^1]

        // ---- stage h chunk (already tf32) ----
#pragma unroll
        for (int it = 0; it < 8; it++) {
            int j = jr + 16 * it;
            float4 hv = *(const float4*)(g_htf + (size_t)(jc + j) * OUTF + f4 * 4);
            *(float4*)(hs + j * HST + f4 * 4) = hv;
        }
        if (t < BJ) sjs[t] = g_sj[jc + t];

        // note: sjs written this iter is consumed this iter -> need visibility.
        // The syncthreads below (before GEMM) is AFTER scores, so guard sjs with
        // a preceding sync: we instead read sjs written LAST iter? No — keep a
        // dedicated sync here.
        __syncthreads();   // hs + sjs visible to all

        // ---- scores -> p = exp(val - m_r), tf32, row-major ps[i][j] ----
#pragma unroll
        for (int kk = 0; kk < 4; kk++) {
            int j0l = (q + 8 * kk) * 4;
            float4 g4 = gv[kk];
            float4 s4 = sv[kk];
            float4 sj4 = *(const float4*)&sjs[j0l];
            uint4 po;
            uint32_t* pd = (uint32_t*)&po;
#pragma unroll
            for (int c = 0; c < 4; c++) {
                float g = (c == 0) ? g4.x : (c == 1) ? g4.y : (c == 2) ? g4.z : g4.w;
                float s = (c == 0) ? s4.x : (c == 1) ? s4.y : (c == 2) ? s4.z : s4.w;
                float sj = (c == 0) ? sj4.x : (c == 1) ? sj4.y : (c == 2) ? sj4.z : sj4.w;
                float cmb = g + s;
                float x = si_r + sj;
                x = (x > 0.f) ? x : LALPHA * x;
                float e = x * cmb;
                float val = (cmb > 0.f) ? e : NEG_BIG;
                float p = __expf(val - m_r);
                l_acc += p;
                pd[c] = f2tf(p);
            }
            *(uint4*)(psb + r * PST + j0l) = po;
        }

        // ---- prefetch next adjacency chunk (lands during GEMM + next staging) ----
        int jn = (ci + 1 < NCH) ? (jc + BJ) : jbase;
        int jb4 = (jn - jbase) >> 2;
#pragma unroll
        for (int kk = 0; kk < 4; kk++) {
            gv[kk] = __ldcs(&gbase[jb4 + q + 8 * kk]);
            sv[kk] = __ldcs(&sbase[jb4 + q + 8 * kk]);
        }

        __syncthreads();   // ps[buf] ready

        // ---- tensor-core GEMM: acc += P[32,128] @ H[128,64] ----
        const float* psA = psb + (m0 + ar) * PST + ac;
        const float* hsB = hs + bk * HST + n0 + bn;
#pragma unroll
        for (int ks = 0; ks < 16; ks++) {
            int k0 = ks * 8;
            uint32_t a0 = __float_as_uint(psA[k0]);
            uint32_t a1 = __float_as_uint(psA[8 * PST + k0]);
            uint32_t a2 = __float_as_uint(psA[k0 + 4]);
            uint32_t a3 = __float_as_uint(psA[8 * PST + k0 + 4]);
#pragma unroll
            for (int nt = 0; nt < 2; nt++) {
                uint32_t b0 = __float_as_uint(hsB[k0 * HST + nt * 8]);
                uint32_t b1 = __float_as_uint(hsB[(k0 + 4) * HST + nt * 8]);
                mma_tf32(acc[nt], a0, a1, a2, a3, b0, b1);
            }
        }
    }

    // ---- partial l: reduce across the 8 threads of each row ----
#pragma unroll
    for (int o = 4; o > 0; o >>= 1)
        l_acc += __shfl_down_sync(0xffffffffu, l_acc, o, 8);
    if (q == 0) g_pl[(size_t)bid * BI + r] = l_acc;

    // ---- partial acc -> global ----
    float* pout = g_pacc + (size_t)bid * BI * OUTF;
    int row0 = m0 + (lane >> 2);
    int col0 = 2 * (lane & 3);
#pragma unroll
    for (int nt = 0; nt < 2; nt++) {
        int col = n0 + nt * 8 + col0;
        *(float2*)(pout + row0 * OUTF + col)       = make_float2(acc[nt][0], acc[nt][1]);
        *(float2*)(pout + (row0 + 8) * OUTF + col) = make_float2(acc[nt][2], acc[nt][3]);
    }
}

// ---------------------------------------------------------------------------
// K3: combine j-split partials, normalize, ELU
// Grid: 128 CTAs x 256 threads; each thread: 1 row x 16 cols.
// ---------------------------------------------------------------------------
__global__ void __launch_bounds__(256) k_fin(float* __restrict__ out) {
    int t = threadIdx.x;
    int i = blockIdx.x * 64 + (t >> 2);     // global row
    int f0 = (t & 3) * 16;
    int tile = i >> 5;
    int r = i & 31;
    const float* pa = g_pacc + (size_t)(2 * tile) * BI * OUTF + r * OUTF + f0;
    const float* pb = pa + BI * OUTF;
    float l = g_pl[(size_t)(2 * tile) * BI + r] + g_pl[(size_t)(2 * tile + 1) * BI + r];
    float inv = 1.f / l;
#pragma unroll
    for (int c4 = 0; c4 < 4; c4++) {
        float4 a4 = *(const float4*)(pa + c4 * 4);
        float4 b4 = *(const float4*)(pb + c4 * 4);
        float4 o;
        float v;
        v = (a4.x + b4.x) * inv; o.x = (v > 0.f) ? v : expm1f(v);
        v = (a4.y + b4.y) * inv; o.y = (v > 0.f) ? v : expm1f(v);
        v = (a4.z + b4.z) * inv; o.z = (v > 0.f) ? v : expm1f(v);
        v = (a4.w + b4.w) * inv; o.w = (v > 0.f) ? v : expm1f(v);
        *(float4*)(out + (size_t)i * OUTF + f0 + c4 * 4) = o;
    }
}

// ---------------------------------------------------------------------------
extern "C" void kernel_launch(void* const* d_in, const int* in_sizes, int n_in,
                              void* d_out, int out_size) {
    const float* geo  = (const float*)d_in[0];
    const float* sem  = (const float*)d_in[1];
    const float* feat = (const float*)d_in[2];
    const float* W    = (const float*)d_in[3];
    const float* avec = (const float*)d_in[4];
    float* out = (float*)d_out;

    k_h<<<Nn / 32, 256>>>(feat, W, avec);

    cudaFuncSetAttribute(k_main, cudaFuncAttributeMaxDynamicSharedMemorySize, SMEM_BYTES);
    k_main<<<(Nn / BI) * JS, TPB, SMEM_BYTES>>>(geo, sem);

    k_fin<<<Nn / 64, 256>>>(out);
}